// round 7
// baseline (speedup 1.0000x reference)
#include <cuda_runtime.h>
#include <cstdint>

// BinLinear: out = input @ sign(tanh(weight)), weight_b in {-1,+1}.
// Identity: out[n,o] = S[n] - 2*T[n,o], S[n]=rowsum(input row n),
//           T[n,o]  = sum of x[n,k] over k where weight[k,o] < 0.
// Exact fp32 products; only summation order differs from reference.
//
// Shapes fixed: M=8192, K=2048 (num_ip), N=2048 (num_op).
// weight row-major [K, N]; input [M, K]; output [M, N] fp32.

#define MDIM 8192
#define KDIM 2048
#define NDIM 2048
#define NQ   (NDIM / 4)      // 512 column quads
#define KB   (KDIM / 8)      // 256 k-groups of 8
#define FULL 0xffffffffu

#define BIN_BLOCKS  512      // binarize: 512 blocks x 256 threads
#define RS_BLOCKS   1024     // rowsum:  1024 blocks x 256 threads (8 rows each)
#define PREP_BLOCKS (BIN_BLOCKS + RS_BLOCKS)   // 1536, interleaved 1:2

// Scratch (no cudaMalloc). Zero-initialized at module load; atomics are
// OR-idempotent so every graph replay reproduces identical state.
// g_mask[kb*NQ + c4]: bit (j*4+e) = sign of weight[kb*8+j][c4*4+e] (1 => -1).
__device__ uint32_t g_mask[KB * NQ];     // 512 KB
__device__ uint32_t g_negq[NQ];          // per-quad OR of mask words (rare path)
__device__ uint32_t g_anyflag;           // nonzero iff any negative weight
__device__ float    g_S[MDIM];           // row sums

// ---------------------------------------------------------------------------
// Fused prep kernel: weight-binarize blocks and input-rowsum blocks in one
// launch, interleaved so both HBM streams are live in every wave.
//   bid % 3 == 0 -> binarize block   (512 of them)
//   otherwise    -> rowsum block     (1024 of them)
// ---------------------------------------------------------------------------
__global__ void __launch_bounds__(256) prep_kernel(const float4* __restrict__ w4,
                                                   const float* __restrict__ x) {
    int bid = blockIdx.x;
    int third = bid / 3;
    int rem = bid - third * 3;

    if (rem == 0) {
        // ---- binarize: thread owns (column quad c4, 8 k's) ----
        int tid = third * 256 + threadIdx.x;
        int c4 = tid & (NQ - 1);        // fastest -> coalesced 16B per lane
        int kb = tid >> 9;              // 0..255
        const float4* base = w4 + (size_t)(kb * 8) * NQ + c4;

        uint32_t bits = 0;
        #pragma unroll
        for (int j = 0; j < 8; j++) {
            float4 v = __ldcs(&base[(size_t)j * NQ]);
            uint32_t b = (uint32_t)(v.x < 0.0f)
                       | ((uint32_t)(v.y < 0.0f) << 1)
                       | ((uint32_t)(v.z < 0.0f) << 2)
                       | ((uint32_t)(v.w < 0.0f) << 3);
            bits |= b << (j * 4);
        }
        g_mask[kb * NQ + c4] = bits;     // coalesced store

        if (bits) {                      // rare path only (idempotent)
            atomicOr(&g_negq[c4], bits);
            atomicOr(&g_anyflag, 1u);
        }
    } else {
        // ---- rowsum: one warp per input row ----
        int rsb = third * 2 + rem - 1;   // 0..1023
        int wid = rsb * 8 + (threadIdx.x >> 5);   // row index
        int lane = threadIdx.x & 31;
        const float4* xrow4 = (const float4*)(x + (size_t)wid * KDIM);

        // Two batches of 8 front-batched loads: MLP=8 in flight while keeping
        // register pressure moderate (v[8] float4 = 32 data regs).
        float s = 0.0f;
        #pragma unroll
        for (int half = 0; half < 2; half++) {
            float4 v[8];
            #pragma unroll
            for (int i = 0; i < 8; i++)
                v[i] = __ldcs(&xrow4[lane + 32 * (half * 8 + i)]);
            #pragma unroll
            for (int i = 0; i < 8; i++)
                s += (v[i].x + v[i].y) + (v[i].z + v[i].w);
        }

        #pragma unroll
        for (int ofs = 16; ofs; ofs >>= 1)
            s += __shfl_xor_sync(FULL, s, ofs);
        if (lane == 0) g_S[wid] = s;
    }
}

// ---------------------------------------------------------------------------
// Fill kernel: one warp per output row. Fast path (no negative weight
// anywhere): broadcast S[n] and issue 16 streaming float4 stores.
// General path: per-quad negq check, O(K) mask scan per affected column.
// ---------------------------------------------------------------------------
__global__ void __launch_bounds__(256) fill_kernel(const float* __restrict__ x,
                                                   float* __restrict__ out) {
    int wid  = blockIdx.x * (blockDim.x >> 5) + (threadIdx.x >> 5);
    int lane = threadIdx.x & 31;

    uint32_t flag = g_anyflag;          // broadcast, L2-hot
    float s = g_S[wid];                 // broadcast per warp
    float4* orow4 = (float4*)(out + (size_t)wid * NDIM);

    if (flag == 0) {
        float4 val = make_float4(s, s, s, s);
        #pragma unroll
        for (int i = 0; i < 16; i++)
            __stcs(&orow4[lane + 32 * i], val);     // pure streaming stores
        return;
    }

    // General path (absent on this dataset, kept exact).
    const float* xrow = x + (size_t)wid * KDIM;
    #pragma unroll 1
    for (int i = 0; i < 16; i++) {
        int c4 = lane + 32 * i;          // quad index; columns c4*4..c4*4+3
        uint32_t q = g_negq[c4];
        float4 val = make_float4(s, s, s, s);
        if (q) {
            float* vp = &val.x;
            #pragma unroll
            for (int e = 0; e < 4; e++) {
                if ((q >> e) & 0x11111111u) {
                    float T = 0.0f;
                    for (int kb = 0; kb < KB; kb++) {
                        uint32_t word = g_mask[kb * NQ + c4];
                        uint32_t sel = (word >> e) & 0x11111111u;
                        while (sel) {
                            int b = __ffs(sel) - 1;     // b = j*4
                            sel &= sel - 1;
                            T += xrow[kb * 8 + (b >> 2)];
                        }
                    }
                    vp[e] = s - 2.0f * T;
                }
            }
        }
        orow4[c4] = val;
    }
}

extern "C" void kernel_launch(void* const* d_in, const int* in_sizes, int n_in,
                              void* d_out, int out_size) {
    const float* input  = (const float*)d_in[0];   // [8192, 2048]
    const float* weight = (const float*)d_in[1];   // [2048, 2048]
    float* out = (float*)d_out;                    // [8192, 2048]

    prep_kernel<<<PREP_BLOCKS, 256>>>((const float4*)weight, input);
    fill_kernel<<<MDIM / 8, 256>>>(input, out);
}